// round 5
// baseline (speedup 1.0000x reference)
#include <cuda_runtime.h>
#include <stdint.h>
#include <math.h>

// Problem constants
#define NIMG 256          // B*F = 16*16
#define HH   224
#define WW   224
#define NPIX (HH*WW)      // 50176
#define NOFF 4
#define NREG (NIMG*NOFF)  // 1024 (image,offset) regions
#define WORDS_PER_REG 32768   // 65536 uint16 bins packed 2-per-uint32

// Static device scratch (no runtime allocation allowed)
__device__ unsigned char d_g[(size_t)NIMG * NPIX];            // 12.8 MB grayscale
__device__ unsigned int  d_hist[(size_t)NREG * WORDS_PER_REG];// 134 MB packed bins (bss -> zero)
__device__ unsigned int  d_s1[NIMG];                          // per-image sum(g)    (zeroed by pass3)
__device__ unsigned int  d_s2[NIMG];                          // per-image sum(g^2)  (zeroed by pass3)
__device__ float d_feat[NREG * 4];                            // per (img,off): con, dis, hom, asm

// ---------------- reductions ----------------
template <typename T>
__device__ __forceinline__ T warp_sum(T v) {
#pragma unroll
    for (int s = 16; s > 0; s >>= 1) v += __shfl_down_sync(0xffffffffu, v, s);
    return v;
}

template <typename T>
__device__ __forceinline__ T block_sum(T v, T* buf) {
    int lane = threadIdx.x & 31;
    int w    = threadIdx.x >> 5;
    v = warp_sum(v);
    if (lane == 0) buf[w] = v;
    __syncthreads();
    int nw = blockDim.x >> 5;
    T r = (threadIdx.x < nw) ? buf[threadIdx.x] : (T)0;
    if (w == 0) r = warp_sum(r);
    __syncthreads();
    return r;  // valid on thread 0
}

// ---------------- pass 1: gray conversion + sum/sumsq ----------------
// x: (B=16, C=3, F=16, H=224, W=224) f32.  4 CTAs per image (1024 total).
// Integer accumulation: g in [0,255]; per-image sum(g^2) <= 3.27e9 < 2^32.
__global__ void __launch_bounds__(256) pass1_gray(const float* __restrict__ x) {
    __shared__ unsigned int rbuf[16];

    int n    = blockIdx.x >> 2;   // image
    int slab = blockIdx.x & 3;    // quarter of the image
    int b = n >> 4, f = n & 15;
    size_t base = ((size_t)(b * 3) * 16 + f) * NPIX;
    const int NV = NPIX / 4;            // 12544 float4 per channel
    const int SL = NV / 4;              // 3136 per slab
    int i0 = slab * SL;

    const float4* p0 = (const float4*)(x + base) + i0;
    const float4* p1 = (const float4*)(x + base + (size_t)16 * NPIX) + i0;
    const float4* p2 = (const float4*)(x + base + (size_t)32 * NPIX) + i0;
    uchar4* g4 = (uchar4*)(d_g + (size_t)n * NPIX) + i0;

    unsigned int s1 = 0, s2 = 0;
    for (int i = threadIdx.x; i < SL; i += blockDim.x) {
        float4 a = p0[i], bb = p1[i], c = p2[i];
        // exact reference order: mean = sum/3 ; g = floor(mean*255)
        int g0 = (int)floorf(((a.x + bb.x + c.x) / 3.0f) * 255.0f);
        int g1 = (int)floorf(((a.y + bb.y + c.y) / 3.0f) * 255.0f);
        int g2 = (int)floorf(((a.z + bb.z + c.z) / 3.0f) * 255.0f);
        int g3 = (int)floorf(((a.w + bb.w + c.w) / 3.0f) * 255.0f);
        g4[i] = make_uchar4((unsigned char)g0, (unsigned char)g1,
                            (unsigned char)g2, (unsigned char)g3);
        s1 += (unsigned int)(g0 + g1 + g2 + g3);
        s2 += (unsigned int)(g0 * g0 + g1 * g1 + g2 * g2 + g3 * g3);
    }
    unsigned int t1 = block_sum<unsigned int>(s1, rbuf);
    unsigned int t2 = block_sum<unsigned int>(s2, rbuf);
    if (threadIdx.x == 0) {
        atomicAdd(&d_s1[n], t1);   // RED.ADD, exact integer -> deterministic
        atomicAdd(&d_s2[n], t2);
    }
}

// ---------------- pass 2: scatter into global packed histogram ----------------
// One CTA per (image, offset). REDG (no-return) atomics into packed uint16 bins.
// Max bin count <= 49952 < 65536 -> low half never carries into high half.
__global__ void __launch_bounds__(512) pass2_scatter() {
    __shared__ float lut[256];
    __shared__ unsigned int rbuf_u[16];
    __shared__ float rbuf_f[16];

    int n = blockIdx.x >> 2;
    int o = blockIdx.x & 3;

    // OFFSETS = [(0,1),(1,1),(1,0),(1,-1)]
    const int drA[4] = {0, 1, 1, 1};
    const int caA[4] = {0, 0, 0, 1};
    const int cbA[4] = {1, 1, 0, 0};
    const int nrA[4] = {224, 223, 223, 223};
    const int ncA[4] = {223, 223, 224, 223};
    int dr = drA[o], ca = caA[o], cb = cbA[o], nr = nrA[o], nc = ncA[o];

    const unsigned char* __restrict__ g = d_g + (size_t)n * NPIX;
    unsigned int* __restrict__ hist = d_hist + (size_t)blockIdx.x * WORDS_PER_REG;

    for (int i = threadIdx.x; i < 256; i += blockDim.x)
        lut[i] = 1.0f / (1.0f + (float)(i * i));
    __syncthreads();

    int lane = threadIdx.x & 31;
    int wrp  = threadIdx.x >> 5;
    int nwrp = blockDim.x >> 5;

    unsigned int sd2 = 0, sad = 0;
    float shom = 0.0f;
    for (int r = wrp; r < nr; r += nwrp) {
        const unsigned char* rowA = g + r * WW + ca;
        const unsigned char* rowB = g + (r + dr) * WW + cb;
        for (int c = lane; c < nc; c += 32) {
            int av = __ldg(&rowA[c]);
            int bv = __ldg(&rowB[c]);
            int k = (av << 8) | bv;
            atomicAdd(&hist[k >> 1], 1u << ((k & 1) << 4));  // REDG, fire-and-forget
            int d = av - bv;
            unsigned int ad = (unsigned int)(d < 0 ? -d : d);
            sd2 += ad * ad;
            sad += ad;
            shom += lut[ad];
        }
    }

    unsigned int t_d2  = block_sum<unsigned int>(sd2, rbuf_u);
    unsigned int t_ad  = block_sum<unsigned int>(sad, rbuf_u);
    float        t_hom = block_sum<float>(shom, rbuf_f);

    if (threadIdx.x == 0) {
        double C = (double)(nr * nc);
        float* out = &d_feat[(size_t)blockIdx.x * 4];
        out[0] = (float)((double)t_d2 / C);   // contrast
        out[1] = (float)((double)t_ad / C);   // dissimilarity
        out[2] = (float)((double)t_hom / C);  // homogeneity
    }
}

// ---------------- pass 3: ASM from histogram; zero histogram behind us ----------------
// One CTA per (image, offset). Loads its 128 KB region into shared, zeroes the
// global region (so the next graph replay starts clean), computes sum (H+H^T)^2.
__global__ void __launch_bounds__(512) pass3_asm() {
    extern __shared__ unsigned int sh[];   // 32768 words = 65536 uint16 bins
    __shared__ unsigned long long rbuf_ull[16];

    unsigned int* __restrict__ hist = d_hist + (size_t)blockIdx.x * WORDS_PER_REG;

    // vectorized copy-in + zero-out
    const uint4 z4 = make_uint4(0u, 0u, 0u, 0u);
    uint4* gh4 = (uint4*)hist;
    uint4* sh4 = (uint4*)sh;
    for (int i = threadIdx.x; i < WORDS_PER_REG / 4; i += blockDim.x) {
        uint4 v = gh4[i];
        sh4[i] = v;
        gh4[i] = z4;
    }
    __syncthreads();

    const unsigned short* h16 = (const unsigned short*)sh;
    unsigned long long sasm = 0ull;
    for (int k = threadIdx.x; k < 65536; k += blockDim.x) {
        int i = k >> 8, j = k & 255;
        unsigned int v = (unsigned int)h16[k] + (unsigned int)h16[(j << 8) | i];
        sasm += (unsigned long long)v * (unsigned long long)v;
    }
    unsigned long long t_asm = block_sum<unsigned long long>(sasm, rbuf_ull);

    if (threadIdx.x == 0) {
        int o = blockIdx.x & 3;
        const int nrA[4] = {224, 223, 223, 223};
        const int ncA[4] = {223, 223, 224, 223};
        double C = (double)(nrA[o] * ncA[o]);
        d_feat[(size_t)blockIdx.x * 4 + 3] = (float)((double)t_asm / (4.0 * C * C));
    }
}

// ---------------- pass 4: std + average offsets, write output; zero s1/s2 ----------------
__global__ void __launch_bounds__(256) pass4_finalize(float* __restrict__ out) {
    int n = threadIdx.x;   // 256 threads = NIMG
    unsigned int s1 = d_s1[n];
    unsigned int s2 = d_s2[n];
    d_s1[n] = 0u;          // reset for next graph replay
    d_s2[n] = 0u;
    double mean = (double)s1 / (double)NPIX;
    double var  = (double)s2 / (double)NPIX - mean * mean;
    if (var < 0.0) var = 0.0;
    float stdv = (float)sqrt(var);

    float con = 0.f, dis = 0.f, hom = 0.f, as = 0.f;
#pragma unroll
    for (int o = 0; o < 4; o++) {
        const float* fp = &d_feat[(size_t)(n * 4 + o) * 4];
        con += fp[0]; dis += fp[1]; hom += fp[2]; as += fp[3];
    }
    con *= 0.25f; dis *= 0.25f; hom *= 0.25f; as *= 0.25f;
    out[n * 6 + 0] = stdv;
    out[n * 6 + 1] = con;
    out[n * 6 + 2] = dis;
    out[n * 6 + 3] = hom;
    out[n * 6 + 4] = as;
    out[n * 6 + 5] = sqrtf(as);
}

extern "C" void kernel_launch(void* const* d_in, const int* in_sizes, int n_in,
                              void* d_out, int out_size) {
    (void)in_sizes; (void)n_in; (void)out_size;
    cudaFuncSetAttribute(pass3_asm, cudaFuncAttributeMaxDynamicSharedMemorySize, 131072);
    const float* x = (const float*)d_in[0];
    float* out = (float*)d_out;
    pass1_gray<<<NIMG * 4, 256>>>(x);
    pass2_scatter<<<NREG, 512>>>();
    pass3_asm<<<NREG, 512, 131072>>>();
    pass4_finalize<<<1, 256>>>(out);
}

// round 7
// speedup vs baseline: 6.6440x; 6.6440x over previous
#include <cuda_runtime.h>
#include <stdint.h>
#include <math.h>

// Problem constants
#define NIMG 256          // B*F = 16*16
#define HH   224
#define WW   224
#define NPIX (HH*WW)      // 50176
#define NOFF 4
#define NREG (NIMG*NOFF)  // 1024

// Static device scratch (+pad: vectorized loads may read up to ~64B past an image)
__device__ unsigned char d_g[(size_t)NIMG * NPIX + 256];
__device__ unsigned int  d_s1[NIMG];   // per-image sum(g)   (zeroed by pass4)
__device__ unsigned int  d_s2[NIMG];   // per-image sum(g^2) (zeroed by pass4)
__device__ float d_feat[NREG * 4];     // per (img,off): con, dis, hom, asm

// ---------------- reductions ----------------
template <typename T>
__device__ __forceinline__ T warp_sum(T v) {
#pragma unroll
    for (int s = 16; s > 0; s >>= 1) v += __shfl_down_sync(0xffffffffu, v, s);
    return v;
}

template <typename T>
__device__ __forceinline__ T block_sum(T v, T* buf) {
    int lane = threadIdx.x & 31;
    int w    = threadIdx.x >> 5;
    v = warp_sum(v);
    if (lane == 0) buf[w] = v;
    __syncthreads();
    int nw = blockDim.x >> 5;
    T r = (threadIdx.x < nw) ? buf[threadIdx.x] : (T)0;
    if (w == 0) r = warp_sum(r);
    __syncthreads();
    return r;  // valid on thread 0
}

// ---------------- pass 1: gray conversion + integer sum/sumsq ----------------
// 4 CTAs per image (1024 total). g in [0,255]; sum(g^2) <= 3.27e9 < 2^32.
__global__ void __launch_bounds__(256) pass1_gray(const float* __restrict__ x) {
    __shared__ unsigned int rbuf[16];

    int n    = blockIdx.x >> 2;
    int slab = blockIdx.x & 3;
    int b = n >> 4, f = n & 15;
    size_t base = ((size_t)(b * 3) * 16 + f) * NPIX;
    const int NV = NPIX / 4;   // 12544 float4 per channel
    const int SL = NV / 4;     // 3136 per slab
    int i0 = slab * SL;

    const float4* p0 = (const float4*)(x + base) + i0;
    const float4* p1 = (const float4*)(x + base + (size_t)16 * NPIX) + i0;
    const float4* p2 = (const float4*)(x + base + (size_t)32 * NPIX) + i0;
    uchar4* g4 = (uchar4*)(d_g + (size_t)n * NPIX) + i0;

    unsigned int s1 = 0, s2 = 0;
    for (int i = threadIdx.x; i < SL; i += blockDim.x) {
        float4 a = p0[i], bb = p1[i], c = p2[i];
        // exact reference order: mean = sum/3 ; g = floor(mean*255)
        int g0 = (int)floorf(((a.x + bb.x + c.x) / 3.0f) * 255.0f);
        int g1 = (int)floorf(((a.y + bb.y + c.y) / 3.0f) * 255.0f);
        int g2 = (int)floorf(((a.z + bb.z + c.z) / 3.0f) * 255.0f);
        int g3 = (int)floorf(((a.w + bb.w + c.w) / 3.0f) * 255.0f);
        g4[i] = make_uchar4((unsigned char)g0, (unsigned char)g1,
                            (unsigned char)g2, (unsigned char)g3);
        s1 += (unsigned int)(g0 + g1 + g2 + g3);
        s2 += (unsigned int)(g0 * g0 + g1 * g1 + g2 * g2 + g3 * g3);
    }
    unsigned int t1 = block_sum<unsigned int>(s1, rbuf);
    unsigned int t2 = block_sum<unsigned int>(s2, rbuf);
    if (threadIdx.x == 0) {
        atomicAdd(&d_s1[n], t1);
        atomicAdd(&d_s2[n], t2);
    }
}

// ---------------- pass 2: GLCM scatter + all 4 features ----------------
// One CTA per (image, offset). 128 KB smem histogram: 65536 uint16 bins packed
// 2-per-uint32, stored ROTATED: bin(i,j) lives in word (i<<7)|(((j>>1)+i)&127),
// half j&1. Row reads conflict-free; transposed reads only 2-way.
// Max bin count <= 50176 < 65536, so halves never carry.
__global__ void __launch_bounds__(512) pass2_glcm() {
    extern __shared__ unsigned int hist[];   // 32768 words
    __shared__ unsigned int rbuf_u[16];
    __shared__ float rbuf_f[16];
    __shared__ unsigned long long rbuf_ull[16];

    int n = blockIdx.x >> 2;
    int o = blockIdx.x & 3;

    // OFFSETS = [(0,1),(1,1),(1,0),(1,-1)]
    // pair at flat idx: a = g[idx+aoff], b = g[idx+boff]; valid iff col(idx) < nc
    const int aoffA[4] = {0, 0, 0, 1};
    const int boffA[4] = {1, 225, 224, 224};
    const int nrA[4]   = {224, 223, 223, 223};
    const int ncA[4]   = {223, 223, 224, 223};
    int aoff = aoffA[o], boff = boffA[o];
    int limit = nrA[o] * WW;     // 50176 or 49952, both divisible by 16
    int nc = ncA[o];

    const unsigned char* __restrict__ g = d_g + (size_t)n * NPIX;

    // zero histogram (vectorized)
    uint4* h4 = (uint4*)hist;
    const uint4 z4 = make_uint4(0u, 0u, 0u, 0u);
    for (int i = threadIdx.x; i < 8192; i += 512) h4[i] = z4;
    __syncthreads();

    // ---- scatter: each thread does 16 consecutive flat pairs per iter ----
    int sha = (aoff & 3) * 8;
    int shb = (boff & 3) * 8;
    int abase = aoff & ~3;
    int bbase = boff & ~3;
    int c = (threadIdx.x * 16) % 224;   // column of this thread's first pair

    for (int base = threadIdx.x * 16; base < limit; base += 8192) {
        const unsigned char* pa = g + base + abase;
        const unsigned char* pb = g + base + bbase;
        uint4 A = *(const uint4*)pa;
        unsigned int A4 = *(const unsigned int*)(pa + 16);
        uint4 B = *(const uint4*)pb;
        unsigned int B4 = *(const unsigned int*)(pb + 16);

        // at most one invalid column (c+p == 223) among the 16 slots
        unsigned int invmask = 0u;
        if (nc == 223) {
            int p = 223 - c;
            if (p < 16) invmask = 1u << p;
        }

        unsigned int aw[5] = {A.x, A.y, A.z, A.w, A4};
        unsigned int bw[5] = {B.x, B.y, B.z, B.w, B4};
#pragma unroll
        for (int j = 0; j < 4; j++) {
            unsigned int sa = __funnelshift_r(aw[j], aw[j + 1], sha);
            unsigned int sb = __funnelshift_r(bw[j], bw[j + 1], shb);
            // keys k = (a<<8)|b for 4 pairs
            unsigned int v0 = __byte_perm(sb, sa, 0x5140);  // pairs 4j, 4j+1
            unsigned int v1 = __byte_perm(sb, sa, 0x7362);  // pairs 4j+2, 4j+3
#pragma unroll
            for (int s = 0; s < 4; s++) {
                unsigned int k = (s == 0) ? (v0 & 0xFFFFu) :
                                 (s == 1) ? (v0 >> 16)     :
                                 (s == 2) ? (v1 & 0xFFFFu) : (v1 >> 16);
                int pos = j * 4 + s;
                if (!((invmask >> pos) & 1u)) {
                    unsigned int i_ = k >> 8;
                    unsigned int jw = (k >> 1) & 127u;
                    unsigned int w  = (i_ << 7) | ((jw + i_) & 127u);
                    atomicAdd(&hist[w], (k & 1u) ? 65536u : 1u);
                }
            }
        }
        c += 128;                 // 8192 mod 224 = 128
        if (c >= 224) c -= 224;
    }
    __syncthreads();

    // ---- features from histogram ----
    // con = sum H*d^2 (u32, <= 3.26e9), dis = sum H*|d| (<= 12.8M),
    // hom = sum H/(1+d^2), asm_num = sum (H[i,j]+H[j,i])^2 (u64)
    unsigned int scon = 0, sdis = 0;
    float shom = 0.0f;
    unsigned long long sasm = 0ull;
    for (int t = threadIdx.x; t < 32768; t += 512) {
        int i  = t >> 7;
        int jw = t & 127;
        unsigned int direct = hist[(i << 7) | ((jw + i) & 127)];
        unsigned int H0 = direct & 0xFFFFu, H1 = direct >> 16;
        int j0 = 2 * jw, j1 = 2 * jw + 1;
        // transposed bins (j0, i) and (j1, i)
        int jTw = i >> 1, half = i & 1;
        unsigned int T0 = hist[(j0 << 7) | ((jTw + j0) & 127)];
        unsigned int T1 = hist[(j1 << 7) | ((jTw + j1) & 127)];
        unsigned int Ht0 = half ? (T0 >> 16) : (T0 & 0xFFFFu);
        unsigned int Ht1 = half ? (T1 >> 16) : (T1 & 0xFFFFu);

        int dd0 = i - j0, dd1 = i - j1;
        unsigned int ad0 = (unsigned int)(dd0 < 0 ? -dd0 : dd0);
        unsigned int ad1 = (unsigned int)(dd1 < 0 ? -dd1 : dd1);
        scon += H0 * ad0 * ad0 + H1 * ad1 * ad1;
        sdis += H0 * ad0 + H1 * ad1;
        shom += (float)H0 * __fdividef(1.0f, 1.0f + (float)(ad0 * ad0)) +
                (float)H1 * __fdividef(1.0f, 1.0f + (float)(ad1 * ad1));
        unsigned int vv0 = H0 + Ht0, vv1 = H1 + Ht1;
        sasm += (unsigned long long)vv0 * vv0 + (unsigned long long)vv1 * vv1;
    }

    unsigned int t_con = block_sum<unsigned int>(scon, rbuf_u);
    unsigned int t_dis = block_sum<unsigned int>(sdis, rbuf_u);
    float        t_hom = block_sum<float>(shom, rbuf_f);
    unsigned long long t_asm = block_sum<unsigned long long>(sasm, rbuf_ull);

    if (threadIdx.x == 0) {
        double C = (double)(nrA[o] * ncA[o]);
        float* out = &d_feat[(size_t)blockIdx.x * 4];
        out[0] = (float)((double)t_con / C);
        out[1] = (float)((double)t_dis / C);
        out[2] = (float)((double)t_hom / C);
        out[3] = (float)((double)t_asm / (4.0 * C * C));
    }
}

// ---------------- pass 4: std + average offsets, write output; reset s1/s2 ----------------
__global__ void __launch_bounds__(256) pass4_finalize(float* __restrict__ out) {
    int n = threadIdx.x;   // 256 threads = NIMG
    unsigned int s1 = d_s1[n];
    unsigned int s2 = d_s2[n];
    d_s1[n] = 0u;
    d_s2[n] = 0u;
    double mean = (double)s1 / (double)NPIX;
    double var  = (double)s2 / (double)NPIX - mean * mean;
    if (var < 0.0) var = 0.0;
    float stdv = (float)sqrt(var);

    float con = 0.f, dis = 0.f, hom = 0.f, as = 0.f;
#pragma unroll
    for (int o = 0; o < 4; o++) {
        const float* fp = &d_feat[(size_t)(n * 4 + o) * 4];
        con += fp[0]; dis += fp[1]; hom += fp[2]; as += fp[3];
    }
    con *= 0.25f; dis *= 0.25f; hom *= 0.25f; as *= 0.25f;
    out[n * 6 + 0] = stdv;
    out[n * 6 + 1] = con;
    out[n * 6 + 2] = dis;
    out[n * 6 + 3] = hom;
    out[n * 6 + 4] = as;
    out[n * 6 + 5] = sqrtf(as);
}

extern "C" void kernel_launch(void* const* d_in, const int* in_sizes, int n_in,
                              void* d_out, int out_size) {
    (void)in_sizes; (void)n_in; (void)out_size;
    cudaFuncSetAttribute(pass2_glcm, cudaFuncAttributeMaxDynamicSharedMemorySize, 131072);
    const float* x = (const float*)d_in[0];
    float* out = (float*)d_out;
    pass1_gray<<<NIMG * 4, 256>>>(x);
    pass2_glcm<<<NREG, 512, 131072>>>();
    pass4_finalize<<<1, 256>>>(out);
}